// round 1
// baseline (speedup 1.0000x reference)
#include <cuda_runtime.h>

// Problem constants (fixed by the reference module)
#define N_  16
#define D_  3
#define H_  160
#define W_  160
#define M_  8
#define K_  10
#define P_  15
#define PM_ 7               // (P-1)/2
#define OH_ (H_ - P_ + 1)   // 146
#define OW_ (W_ - P_ + 1)   // 146
#define MK_ (M_ * K_)       // 80
#define PLANE_ (OH_ * OW_)  // 21316

__global__ void fern_bits_kernel(
    const float* __restrict__ T,
    const float* __restrict__ dx1, const float* __restrict__ dx2,
    const float* __restrict__ dy1, const float* __restrict__ dy2,
    const float* __restrict__ th,  const float* __restrict__ amb,
    const int*   __restrict__ channels,
    float* __restrict__ out)
{
    const int nmk = blockIdx.y;         // n*MK + mk
    const int n   = nmk / MK_;
    const int mk  = nmk - n * MK_;
    const int m   = mk / K_;
    const int k   = mk - m * K_;
    const int ch  = channels[k];        // ch tiled over M: ch[mk] = channels[mk % K]

    // Per-(m,k) parameters — uniform across the block (broadcast loads)
    const float a1x = dx1[mk], a2x = dx2[mk];
    const float a1y = dy1[mk], a2y = dy2[mk];
    const float fl1x = floorf(a1x), fl2x = floorf(a2x);
    const float fl1y = floorf(a1y), fl2y = floorf(a2y);
    const float f1x = a1x - fl1x, f2x = a2x - fl2x;   // frac in [0,1) == abs form
    const float f1y = a1y - fl1y, f2y = a2y - fl2y;
    const int sx1 = PM_ + (int)fl1x, sx2 = PM_ + (int)fl2x;
    const int sy1 = PM_ + (int)fl1y, sy2 = PM_ + (int)fl2y;

    const float thv = th[mk];
    const float pos = amb[(m * 2 + 0) * K_ + k];
    const float neg = amb[(m * 2 + 1) * K_ + k];
    const float inv = 1.0f / (pos - neg + 1e-29f);

    const int idx = blockIdx.x * blockDim.x + threadIdx.x;
    if (idx >= PLANE_) return;
    const int y = idx / OW_;
    const int x = idx - y * OW_;

    // Base pointer for this (n, ch) image plane. No padding needed:
    // sy,sx in [0,12]  =>  max index = 12 + 145 + 1 = 158 < 160.
    const float* __restrict__ img = T + ((size_t)(n * D_ + ch)) * (H_ * W_);

    // Sample 1 (bilinear, 4 taps)
    const float* p1 = img + (sy1 + y) * W_ + (sx1 + x);
    const float v00a = __ldg(p1);
    const float v01a = __ldg(p1 + 1);
    const float v10a = __ldg(p1 + W_);
    const float v11a = __ldg(p1 + W_ + 1);
    const float s1 = (1.0f - f1y) * ((1.0f - f1x) * v00a + f1x * v01a)
                   +         f1y  * ((1.0f - f1x) * v10a + f1x * v11a);

    // Sample 2
    const float* p2 = img + (sy2 + y) * W_ + (sx2 + x);
    const float v00b = __ldg(p2);
    const float v01b = __ldg(p2 + 1);
    const float v10b = __ldg(p2 + W_);
    const float v11b = __ldg(p2 + W_ + 1);
    const float s2 = (1.0f - f2y) * ((1.0f - f2x) * v00b + f2x * v01b)
                   +         f2y  * ((1.0f - f2x) * v10b + f2x * v11b);

    float temp = s1 - s2;
    if (fabsf(temp) < 1e-5f) temp = 0.0f;
    const float b = temp - thv;
    float v = (b - neg) * inv;
    v = fminf(fmaxf(v, 0.0f), 1.0f);

    out[(size_t)nmk * PLANE_ + idx] = v;
}

extern "C" void kernel_launch(void* const* d_in, const int* in_sizes, int n_in,
                              void* d_out, int out_size)
{
    // metadata order: T, dx1, dx2, dy1, dy2, th, amb, channels, patch_size
    const float* T        = (const float*)d_in[0];
    const float* dx1      = (const float*)d_in[1];
    const float* dx2      = (const float*)d_in[2];
    const float* dy1      = (const float*)d_in[3];
    const float* dy2      = (const float*)d_in[4];
    const float* th       = (const float*)d_in[5];
    const float* amb      = (const float*)d_in[6];
    const int*   channels = (const int*)  d_in[7];
    float* out = (float*)d_out;

    const int threads = 256;
    dim3 grid((PLANE_ + threads - 1) / threads, N_ * MK_);
    fern_bits_kernel<<<grid, threads>>>(T, dx1, dx2, dy1, dy2, th, amb, channels, out);
}

// round 2
// speedup vs baseline: 1.6228x; 1.6228x over previous
#include <cuda_runtime.h>

// Problem constants (fixed by the reference module)
#define N_  16
#define D_  3
#define H_  160
#define W_  160
#define M_  8
#define K_  10
#define P_  15
#define PM_ 7               // (P-1)/2
#define OH_ (H_ - P_ + 1)   // 146
#define OW_ (W_ - P_ + 1)   // 146
#define MK_ (M_ * K_)       // 80
#define PLANE_ (OH_ * OW_)  // 21316
#define GX_ 37              // ceil(146/4) groups along x
#define GY_ 73              // 146/2 groups along y
#define NGROUP_ (GX_ * GY_) // 2701 tiles per plane

__global__ __launch_bounds__(128)
void fern_bits_kernel(
    const float* __restrict__ T,
    const float* __restrict__ dx1, const float* __restrict__ dx2,
    const float* __restrict__ dy1, const float* __restrict__ dy2,
    const float* __restrict__ th,  const float* __restrict__ amb,
    const int*   __restrict__ channels,
    float* __restrict__ out)
{
    const int nmk = blockIdx.y;         // n*MK + mk
    const int n   = nmk / MK_;
    const int mk  = nmk - n * MK_;
    const int m   = mk / K_;
    const int k   = mk - m * K_;
    const int ch  = channels[k];

    // Per-(m,k) parameters — uniform across the block (broadcast loads)
    const float a1x = dx1[mk], a2x = dx2[mk];
    const float a1y = dy1[mk], a2y = dy2[mk];
    const float fl1x = floorf(a1x), fl2x = floorf(a2x);
    const float fl1y = floorf(a1y), fl2y = floorf(a2y);
    const float f1x = a1x - fl1x, f2x = a2x - fl2x;
    const float f1y = a1y - fl1y, f2y = a2y - fl2y;
    const int sx1 = PM_ + (int)fl1x, sx2 = PM_ + (int)fl2x;
    const int sy1 = PM_ + (int)fl1y, sy2 = PM_ + (int)fl2y;

    const float thv = th[mk];
    const float pos = amb[(m * 2 + 0) * K_ + k];
    const float neg = amb[(m * 2 + 1) * K_ + k];
    const float inv = 1.0f / (pos - neg + 1e-29f);
    const float off = thv + neg;        // out = clip((temp - off)*inv)

    const int gid = blockIdx.x * blockDim.x + threadIdx.x;
    if (gid >= NGROUP_) return;
    const int gy = gid / GX_;
    const int gx = gid - gy * GX_;
    const int y0 = gy * 2;
    const int x0 = gx * 4;

    // No padding needed: sy,sx in [0,12]; worst read index
    // (12+144+2)*160 + 12+148+... stays inside the 160x160 plane.
    const float* __restrict__ img = T + ((size_t)(n * D_ + ch)) * (H_ * W_);

    float s[2][4];

    // ---- sample 1: 3x5 tap footprint, separable lerp ----
    {
        const float* p = img + (sy1 + y0) * W_ + (sx1 + x0);
        const float g1y = 1.0f - f1y, g1x = 1.0f - f1x;
        float c0[5], c1[5];
        #pragma unroll
        for (int j = 0; j < 5; j++) {
            const float r0 = __ldg(p + j);
            const float r1 = __ldg(p + W_ + j);
            const float r2 = __ldg(p + 2 * W_ + j);
            c0[j] = g1y * r0 + f1y * r1;
            c1[j] = g1y * r1 + f1y * r2;
        }
        #pragma unroll
        for (int i = 0; i < 4; i++) {
            s[0][i] = g1x * c0[i] + f1x * c0[i + 1];
            s[1][i] = g1x * c1[i] + f1x * c1[i + 1];
        }
    }

    // ---- sample 2: subtract in place ----
    {
        const float* p = img + (sy2 + y0) * W_ + (sx2 + x0);
        const float g2y = 1.0f - f2y, g2x = 1.0f - f2x;
        float c0[5], c1[5];
        #pragma unroll
        for (int j = 0; j < 5; j++) {
            const float r0 = __ldg(p + j);
            const float r1 = __ldg(p + W_ + j);
            const float r2 = __ldg(p + 2 * W_ + j);
            c0[j] = g2y * r0 + f2y * r1;
            c1[j] = g2y * r1 + f2y * r2;
        }
        #pragma unroll
        for (int i = 0; i < 4; i++) {
            s[0][i] -= g2x * c0[i] + f2x * c0[i + 1];
            s[1][i] -= g2x * c1[i] + f2x * c1[i + 1];
        }
    }

    // ---- epilogue: deadzone, threshold, normalize, clamp ----
    #pragma unroll
    for (int r = 0; r < 2; r++) {
        #pragma unroll
        for (int i = 0; i < 4; i++) {
            float temp = s[r][i];
            if (fabsf(temp) < 1e-5f) temp = 0.0f;
            float v = (temp - off) * inv;
            s[r][i] = fminf(fmaxf(v, 0.0f), 1.0f);
        }
    }

    // ---- stores: float2, always 8B-aligned (row starts even, x0 % 4 == 0) ----
    float* op = out + (size_t)nmk * PLANE_ + y0 * OW_ + x0;
    if (x0 + 4 <= OW_) {
        #pragma unroll
        for (int r = 0; r < 2; r++) {
            *(float2*)(op + r * OW_)     = make_float2(s[r][0], s[r][1]);
            *(float2*)(op + r * OW_ + 2) = make_float2(s[r][2], s[r][3]);
        }
    } else {  // tail column group: x0 == 144, 2 valid columns
        #pragma unroll
        for (int r = 0; r < 2; r++) {
            *(float2*)(op + r * OW_) = make_float2(s[r][0], s[r][1]);
        }
    }
}

extern "C" void kernel_launch(void* const* d_in, const int* in_sizes, int n_in,
                              void* d_out, int out_size)
{
    const float* T        = (const float*)d_in[0];
    const float* dx1      = (const float*)d_in[1];
    const float* dx2      = (const float*)d_in[2];
    const float* dy1      = (const float*)d_in[3];
    const float* dy2      = (const float*)d_in[4];
    const float* th       = (const float*)d_in[5];
    const float* amb      = (const float*)d_in[6];
    const int*   channels = (const int*)  d_in[7];
    float* out = (float*)d_out;

    const int threads = 128;
    dim3 grid((NGROUP_ + threads - 1) / threads, N_ * MK_);
    fern_bits_kernel<<<grid, threads>>>(T, dx1, dx2, dy1, dy2, th, amb, channels, out);
}

// round 3
// speedup vs baseline: 2.6857x; 1.6550x over previous
#include <cuda_runtime.h>

// Problem constants (fixed by the reference module)
#define N_  16
#define D_  3
#define H_  160
#define W_  160
#define M_  8
#define K_  10
#define P_  15
#define PM_ 7               // (P-1)/2
#define OH_ (H_ - P_ + 1)   // 146
#define OW_ (W_ - P_ + 1)   // 146
#define MK_ (M_ * K_)       // 80
#define PLANE_ (OH_ * OW_)  // 21316

#define HTILE_ 8                       // output rows per thread
#define CG_    5                       // ceil(146/32) column groups (32 cols each)
#define RG_    19                      // ceil(146/8) row groups
#define WARPS_PER_PLANE_ (CG_ * RG_)   // 95
#define WARPS_PER_BLOCK_ 8
#define BLOCKS_X_ ((WARPS_PER_PLANE_ + WARPS_PER_BLOCK_ - 1) / WARPS_PER_BLOCK_)  // 12

__global__ __launch_bounds__(WARPS_PER_BLOCK_ * 32)
void fern_bits_kernel(
    const float* __restrict__ T,
    const float* __restrict__ dx1, const float* __restrict__ dx2,
    const float* __restrict__ dy1, const float* __restrict__ dy2,
    const float* __restrict__ th,  const float* __restrict__ amb,
    const int*   __restrict__ channels,
    float* __restrict__ out)
{
    const int nmk = blockIdx.y;         // n*MK + mk
    const int n   = nmk / MK_;
    const int mk  = nmk - n * MK_;
    const int m   = mk / K_;
    const int k   = mk - m * K_;
    const int ch  = channels[k];

    // Per-(m,k) parameters — uniform (broadcast loads)
    const float a1x = dx1[mk], a2x = dx2[mk];
    const float a1y = dy1[mk], a2y = dy2[mk];
    const float fl1x = floorf(a1x), fl2x = floorf(a2x);
    const float fl1y = floorf(a1y), fl2y = floorf(a2y);
    const float f1x = a1x - fl1x, f2x = a2x - fl2x;
    const float f1y = a1y - fl1y, f2y = a2y - fl2y;
    const int sx1 = PM_ + (int)fl1x, sx2 = PM_ + (int)fl2x;
    const int sy1 = PM_ + (int)fl1y, sy2 = PM_ + (int)fl2y;

    const float thv = th[mk];
    const float pos = amb[(m * 2 + 0) * K_ + k];
    const float neg = amb[(m * 2 + 1) * K_ + k];
    const float inv = 1.0f / (pos - neg + 1e-29f);
    const float off = thv + neg;        // out = clip((temp - off)*inv, 0, 1)

    // Warp tiling: 32 columns x HTILE_ rows per warp, lane = column
    const int wp = blockIdx.x * WARPS_PER_BLOCK_ + (threadIdx.x >> 5);
    if (wp >= WARPS_PER_PLANE_) return;
    const int cg = wp % CG_;
    const int rg = wp / CG_;
    const int x  = cg * 32 + (threadIdx.x & 31);
    const int y0 = rg * HTILE_;
    const int hv = min(HTILE_, OH_ - y0);     // 8, or 2 for the last row group
    const bool valid = (x < OW_);

    // In-bounds guarantee for valid lanes: sy,sx in [0,12];
    // max row = 12 + 145 + 1 = 158 < 160, max col = 158 < 160.
    const float* __restrict__ img = T + ((size_t)(n * D_ + ch)) * (H_ * W_);

    float s[HTILE_];

    if (valid) {
        // ---- sample 1: horizontal lerp per input row, then vertical lerps ----
        {
            const float g1y = 1.0f - f1y, g1x = 1.0f - f1x;
            const float* p = img + (sy1 + y0) * W_ + (sx1 + x);
            float hl[HTILE_ + 1];
            #pragma unroll
            for (int r = 0; r <= HTILE_; r++) {
                if (r <= hv) {
                    const float v0 = __ldg(p + r * W_);
                    const float v1 = __ldg(p + r * W_ + 1);
                    hl[r] = g1x * v0 + f1x * v1;
                }
            }
            #pragma unroll
            for (int j = 0; j < HTILE_; j++)
                if (j < hv) s[j] = g1y * hl[j] + f1y * hl[j + 1];
        }

        // ---- sample 2: subtract in place ----
        {
            const float g2y = 1.0f - f2y, g2x = 1.0f - f2x;
            const float* p = img + (sy2 + y0) * W_ + (sx2 + x);
            float hl[HTILE_ + 1];
            #pragma unroll
            for (int r = 0; r <= HTILE_; r++) {
                if (r <= hv) {
                    const float v0 = __ldg(p + r * W_);
                    const float v1 = __ldg(p + r * W_ + 1);
                    hl[r] = g2x * v0 + f2x * v1;
                }
            }
            #pragma unroll
            for (int j = 0; j < HTILE_; j++)
                if (j < hv) s[j] -= g2y * hl[j] + f2y * hl[j + 1];
        }

        // ---- epilogue + coalesced scalar stores ----
        float* op = out + (size_t)nmk * PLANE_ + y0 * OW_ + x;
        #pragma unroll
        for (int j = 0; j < HTILE_; j++) {
            if (j < hv) {
                float temp = s[j];
                if (fabsf(temp) < 1e-5f) temp = 0.0f;
                float v = (temp - off) * inv;
                op[j * OW_] = fminf(fmaxf(v, 0.0f), 1.0f);
            }
        }
    }
}

extern "C" void kernel_launch(void* const* d_in, const int* in_sizes, int n_in,
                              void* d_out, int out_size)
{
    const float* T        = (const float*)d_in[0];
    const float* dx1      = (const float*)d_in[1];
    const float* dx2      = (const float*)d_in[2];
    const float* dy1      = (const float*)d_in[3];
    const float* dy2      = (const float*)d_in[4];
    const float* th       = (const float*)d_in[5];
    const float* amb      = (const float*)d_in[6];
    const int*   channels = (const int*)  d_in[7];
    float* out = (float*)d_out;

    dim3 grid(BLOCKS_X_, N_ * MK_);
    fern_bits_kernel<<<grid, WARPS_PER_BLOCK_ * 32>>>(
        T, dx1, dx2, dy1, dy2, th, amb, channels, out);
}